// round 11
// baseline (speedup 1.0000x reference)
#include <cuda_runtime.h>
#include <cuda_fp16.h>

// Problem constants
#define KCLS  256
#define NTOT  24000              // BS*Q rows
#define TTOT  2400               // targets
#define NQUAD (TTOT / 4)         // 600 quads of 4 targets
#define TPB   128
#define NBLK  2368               // 148 SMs x 8 blocks x 2 = EXACTLY two waves
#define RMAX  11                 // 320 blocks w/ 11 rows + 2048 w/ 10 = 24000
#define RSTR  14                 // padded r-stride of transposed class table
                                 // (even -> LDS.64 aligned; gcd(14,32)=2 -> spread)

static __device__ __forceinline__ half2 h2_from_f(float f) {
    return *reinterpret_cast<half2*>(&f);
}
static __device__ __forceinline__ float f_from_h2(half2 h) {
    return *reinterpret_cast<float*>(&h);
}

// ---------------------------------------------------------------------------
// Fused kernel; transposed class table: one LDS.64 per id serves 2 rows.
// Inner loop processes 2 rows per iteration (5 pairs; +1 tail row if R=11).
// All geometry x5-scaled (L1 sum = 5*L1 directly; GIoU scale-invariant).
// ---------------------------------------------------------------------------
__global__ __launch_bounds__(TPB, 8) void fused_kernel(
    const float* __restrict__ logits,       // [NTOT, 256]
    const float* __restrict__ pred_boxes,   // [NTOT, 4] cxcywh
    const float* __restrict__ tgt_bbox,     // [TTOT, 4] cxcywh
    const int*   __restrict__ tgt_ids,      // [TTOT]
    float*       __restrict__ out)          // [NTOT, TTOT]
{
    __shared__ float  s_diffT[KCLS * RSTR];        // 14336 B, [k][r] transposed
    __shared__ float4 s_pd[RMAX][2];               //   352 B

    const int tid = threadIdx.x;
    const int b   = blockIdx.x;
    const int n0  = b * 10 + min(b, 320);
    const int R   = (b < 320) ? 11 : 10;

    // ---- preamble A: class-cost table, TRANSPOSED: s_diffT[k][r] = focal+2
    const float4* lg4 = reinterpret_cast<const float4*>(logits) + n0 * (KCLS / 4);
    for (int i = tid; i < R * (KCLS / 4); i += TPB) {
        const int r  = i >> 6;                     // row within block tile
        const int k0 = (i & 63) << 2;              // first of 4 classes
        float4 x4 = lg4[i];
        const float* xs = &x4.x;
        #pragma unroll
        for (int j = 0; j < 4; j++) {
            float x   = xs[j];
            float ex  = __expf(-x);
            float L   = __logf(1.0f + ex);                // = -log(p)
            float p   = __frcp_rn(1.0f + ex);
            float omp = 1.0f - p;
            float pos = 0.25f * omp * omp * L;            // A(1-p)^2 * -log p
            float neg = 0.75f * p * p * (x + L);          // (1-A) p^2 * -log(1-p)
            s_diffT[(k0 + j) * RSTR + r] = pos - neg + 2.0f;
        }
    }

    // ---- preamble B: pred boxes -> x5-scaled half2 splats
    if (tid < R) {
        float4 pb = reinterpret_cast<const float4*>(pred_boxes)[n0 + tid];
        pb.x *= 5.0f; pb.y *= 5.0f; pb.z *= 5.0f; pb.w *= 5.0f;
        s_pd[tid][0] = make_float4(f_from_h2(__float2half2_rn(pb.x)),
                                   f_from_h2(__float2half2_rn(pb.y)),
                                   f_from_h2(__float2half2_rn(pb.z)),
                                   f_from_h2(__float2half2_rn(pb.w)));
        s_pd[tid][1] = make_float4(f_from_h2(__float2half2_rn(pb.x - 0.5f * pb.z)),
                                   f_from_h2(__float2half2_rn(pb.y - 0.5f * pb.w)),
                                   f_from_h2(__float2half2_rn(pb.x + 0.5f * pb.z)),
                                   f_from_h2(__float2half2_rn(pb.y + 0.5f * pb.w)));
    }
    __syncthreads();

    const half2 zero2 = __float2half2_rn(0.0f);
    const half2 m2    = __float2half2_rn(-2.0f);

    for (int q = tid; q < NQUAD; q += TPB) {
        // ---- 4 target ids -> word offsets into transposed table ----
        int4 id4 = reinterpret_cast<const int4*>(tgt_ids)[q];
        const int a0 = id4.x * RSTR, a1 = id4.y * RSTR,
                  a2 = id4.z * RSTR, a3 = id4.w * RSTR;

        // ---- load + derive 4 targets (x5-scaled, once per quad) ----
        half2 tcx2[2], tcy2[2], tw2[2], th2[2];
        half2 tx0_2[2], ty0_2[2], tx1_2[2], ty1_2[2], ta_2[2];
        #pragma unroll
        for (int g = 0; g < 2; g++) {
            float4 a  = reinterpret_cast<const float4*>(tgt_bbox)[4 * q + 2 * g];
            float4 bx = reinterpret_cast<const float4*>(tgt_bbox)[4 * q + 2 * g + 1];
            a.x *= 5.0f;  a.y *= 5.0f;  a.z *= 5.0f;  a.w *= 5.0f;
            bx.x *= 5.0f; bx.y *= 5.0f; bx.z *= 5.0f; bx.w *= 5.0f;
            tcx2[g]  = __floats2half2_rn(a.x, bx.x);
            tcy2[g]  = __floats2half2_rn(a.y, bx.y);
            tw2[g]   = __floats2half2_rn(a.z, bx.z);
            th2[g]   = __floats2half2_rn(a.w, bx.w);
            tx0_2[g] = __floats2half2_rn(a.x - 0.5f * a.z, bx.x - 0.5f * bx.z);
            ty0_2[g] = __floats2half2_rn(a.y - 0.5f * a.w, bx.y - 0.5f * bx.w);
            tx1_2[g] = __floats2half2_rn(a.x + 0.5f * a.z, bx.x + 0.5f * bx.z);
            ty1_2[g] = __floats2half2_rn(a.y + 0.5f * a.w, bx.y + 0.5f * bx.w);
            ta_2[g]  = __floats2half2_rn(a.z * a.w,        bx.z * bx.w);
        }

        // one row evaluation: hv[] = 5*L1 - 2*(i/u + u/e) per target
        auto eval_row = [&](int r, float c0, float c1, float c2, float c3) {
            const float4 f0 = s_pd[r][0];
            const float4 f1 = s_pd[r][1];
            const half2 pcx2  = h2_from_f(f0.x);
            const half2 pcy2  = h2_from_f(f0.y);
            const half2 pw2   = h2_from_f(f0.z);
            const half2 ph2   = h2_from_f(f0.w);
            const half2 px0_2 = h2_from_f(f1.x);
            const half2 py0_2 = h2_from_f(f1.y);
            const half2 px1_2 = h2_from_f(f1.z);
            const half2 py1_2 = h2_from_f(f1.w);
            const half2 pa_2  = __hmul2(pw2, ph2);

            float hv[4];
            #pragma unroll
            for (int g = 0; g < 2; g++) {
                half2 l15 = __hadd2(
                    __hadd2(__habs2(__hsub2(pcx2, tcx2[g])),
                            __habs2(__hsub2(pcy2, tcy2[g]))),
                    __hadd2(__habs2(__hsub2(pw2,  tw2[g])),
                            __habs2(__hsub2(ph2,  th2[g]))));
                half2 diw = __hsub2(__hmin2(px1_2, tx1_2[g]),
                                    __hmax2(px0_2, tx0_2[g]));
                half2 dih = __hsub2(__hmin2(py1_2, ty1_2[g]),
                                    __hmax2(py0_2, ty0_2[g]));
                half2 inter = __hmul2(__hmax2(diw, zero2), __hmax2(dih, zero2));
                half2 uni   = __hsub2(__hadd2(pa_2, ta_2[g]), inter);
                half2 ew  = __hsub2(__hadd2(pw2, tw2[g]), diw);
                half2 eh  = __hsub2(__hadd2(ph2, th2[g]), dih);
                half2 ea  = __hmul2(ew, eh);
                half2 tm  = __hfma2(uni, h2rcp(ea), __hmul2(inter, h2rcp(uni)));
                half2 h   = __hfma2(tm, m2, l15);
                hv[2 * g]     = __low2float(h);
                hv[2 * g + 1] = __high2float(h);
            }
            reinterpret_cast<float4*>(out)[(n0 + r) * NQUAD + q] =
                make_float4(hv[0] + c0, hv[1] + c1, hv[2] + c2, hv[3] + c3);
        };

        // ---- 5 row-pairs (rows 0..9): one LDS.64 per id per pair ----
        #pragma unroll 1
        for (int p = 0; p < 5; p++) {
            const int r0 = 2 * p;
            float2 cA = *reinterpret_cast<const float2*>(&s_diffT[a0 + r0]);
            float2 cB = *reinterpret_cast<const float2*>(&s_diffT[a1 + r0]);
            float2 cC = *reinterpret_cast<const float2*>(&s_diffT[a2 + r0]);
            float2 cD = *reinterpret_cast<const float2*>(&s_diffT[a3 + r0]);
            eval_row(r0,     cA.x, cB.x, cC.x, cD.x);
            eval_row(r0 + 1, cA.y, cB.y, cC.y, cD.y);
        }
        // ---- tail row 10 (only when R == 11): scalar gathers ----
        if (R == 11) {
            eval_row(10, s_diffT[a0 + 10], s_diffT[a1 + 10],
                         s_diffT[a2 + 10], s_diffT[a3 + 10]);
        }
    }
}

// ---------------------------------------------------------------------------
extern "C" void kernel_launch(void* const* d_in, const int* in_sizes, int n_in,
                              void* d_out, int out_size)
{
    const float* pred_logits = (const float*)d_in[0];  // [16,1500,256]
    const float* pred_boxes  = (const float*)d_in[1];  // [16,1500,4]
    const float* tgt_bbox    = (const float*)d_in[2];  // [2400,4]
    const int*   tgt_ids     = (const int*)  d_in[3];  // [2400]
    float*       out         = (float*)d_out;          // [16,1500,2400]

    fused_kernel<<<NBLK, TPB>>>(pred_logits, pred_boxes, tgt_bbox,
                                tgt_ids, out);
}

// round 13
// speedup vs baseline: 1.0107x; 1.0107x over previous
#include <cuda_runtime.h>
#include <cuda_fp16.h>
#include <cstdint>

// Problem constants
#define KCLS  256
#define NTOT  24000              // BS*Q rows
#define TTOT  2400               // targets
#define NQUAD (TTOT / 4)         // 600 quads of 4 targets
#define TPB   128
#define NBLK  2664               // 148 SMs x 9 blocks x 2 = EXACTLY two waves
#define RMAX  10                 // 24 blocks w/ 10 rows + 2640 w/ 9 = 24000
#define RSTR  12                 // halves per class row (24 B, 4B-aligned pairs)

typedef unsigned int u32;

static __device__ __forceinline__ half2 h2_from_f(float f) {
    return *reinterpret_cast<half2*>(&f);
}
static __device__ __forceinline__ float f_from_h2(half2 h) {
    return *reinterpret_cast<float*>(&h);
}
static __device__ __forceinline__ half2 h2_from_u(u32 u) {
    return *reinterpret_cast<half2*>(&u);
}

// ---------------------------------------------------------------------------
// Fused kernel (R7 shell): grid 2664 = 2 exact waves, 9 blocks/SM.
// Class table stored TRANSPOSED in fp16: s_diffTh[k][r]. One LDS.U32 per id
// serves 2 rows; PRMT re-packs per-row half2 pairs; epilogue adds in half2.
// All geometry x5-scaled (L1 sum = 5*L1; GIoU scale-invariant).
// ---------------------------------------------------------------------------
__global__ __launch_bounds__(TPB, 9) void fused_kernel(
    const float* __restrict__ logits,       // [NTOT, 256]
    const float* __restrict__ pred_boxes,   // [NTOT, 4] cxcywh
    const float* __restrict__ tgt_bbox,     // [TTOT, 4] cxcywh
    const int*   __restrict__ tgt_ids,      // [TTOT]
    float*       __restrict__ out)          // [NTOT, TTOT]
{
    __shared__ half   s_diffTh[KCLS * RSTR];       // 6144 B, [k][r] fp16
    __shared__ float4 s_pd[RMAX][2];               //  320 B

    const int tid = threadIdx.x;
    const int b   = blockIdx.x;
    const int n0  = b * 9 + min(b, 24);
    const int R   = (b < 24) ? 10 : 9;

    // ---- preamble A: transposed fp16 class-cost table: focal(pos-neg)+2
    const float4* lg4 = reinterpret_cast<const float4*>(logits) + n0 * (KCLS / 4);
    for (int i = tid; i < R * (KCLS / 4); i += TPB) {
        const int r  = i >> 6;                     // row within block tile
        const int k0 = (i & 63) << 2;              // first of 4 classes
        float4 x4 = lg4[i];
        const float* xs = &x4.x;
        #pragma unroll
        for (int j = 0; j < 4; j++) {
            float x   = xs[j];
            float ex  = __expf(-x);
            float L   = __logf(1.0f + ex);                // = -log(p)
            float p   = __frcp_rn(1.0f + ex);
            float omp = 1.0f - p;
            float pos = 0.25f * omp * omp * L;            // A(1-p)^2 * -log p
            float neg = 0.75f * p * p * (x + L);          // (1-A) p^2 * -log(1-p)
            s_diffTh[(k0 + j) * RSTR + r] = __float2half_rn(pos - neg + 2.0f);
        }
    }

    // ---- preamble B: pred boxes -> x5-scaled half2 splats
    if (tid < R) {
        float4 pb = reinterpret_cast<const float4*>(pred_boxes)[n0 + tid];
        pb.x *= 5.0f; pb.y *= 5.0f; pb.z *= 5.0f; pb.w *= 5.0f;
        s_pd[tid][0] = make_float4(f_from_h2(__float2half2_rn(pb.x)),
                                   f_from_h2(__float2half2_rn(pb.y)),
                                   f_from_h2(__float2half2_rn(pb.z)),
                                   f_from_h2(__float2half2_rn(pb.w)));
        s_pd[tid][1] = make_float4(f_from_h2(__float2half2_rn(pb.x - 0.5f * pb.z)),
                                   f_from_h2(__float2half2_rn(pb.y - 0.5f * pb.w)),
                                   f_from_h2(__float2half2_rn(pb.x + 0.5f * pb.z)),
                                   f_from_h2(__float2half2_rn(pb.y + 0.5f * pb.w)));
    }
    __syncthreads();

    const half2 zero2 = __float2half2_rn(0.0f);
    const half2 m2    = __float2half2_rn(-2.0f);

    for (int q = tid; q < NQUAD; q += TPB) {
        // ---- 4 per-quad base pointers into the transposed fp16 table ----
        int4 id4 = reinterpret_cast<const int4*>(tgt_ids)[q];
        const u32* pA = reinterpret_cast<const u32*>(s_diffTh + id4.x * RSTR);
        const u32* pB = reinterpret_cast<const u32*>(s_diffTh + id4.y * RSTR);
        const u32* pC = reinterpret_cast<const u32*>(s_diffTh + id4.z * RSTR);
        const u32* pD = reinterpret_cast<const u32*>(s_diffTh + id4.w * RSTR);

        // ---- load + derive 4 targets (x5-scaled, once per quad) ----
        half2 tcx2[2], tcy2[2], tw2[2], th2[2];
        half2 tx0_2[2], ty0_2[2], tx1_2[2], ty1_2[2], ta_2[2];
        #pragma unroll
        for (int g = 0; g < 2; g++) {
            float4 a  = reinterpret_cast<const float4*>(tgt_bbox)[4 * q + 2 * g];
            float4 bx = reinterpret_cast<const float4*>(tgt_bbox)[4 * q + 2 * g + 1];
            a.x *= 5.0f;  a.y *= 5.0f;  a.z *= 5.0f;  a.w *= 5.0f;
            bx.x *= 5.0f; bx.y *= 5.0f; bx.z *= 5.0f; bx.w *= 5.0f;
            tcx2[g]  = __floats2half2_rn(a.x, bx.x);
            tcy2[g]  = __floats2half2_rn(a.y, bx.y);
            tw2[g]   = __floats2half2_rn(a.z, bx.z);
            th2[g]   = __floats2half2_rn(a.w, bx.w);
            tx0_2[g] = __floats2half2_rn(a.x - 0.5f * a.z, bx.x - 0.5f * bx.z);
            ty0_2[g] = __floats2half2_rn(a.y - 0.5f * a.w, bx.y - 0.5f * bx.w);
            tx1_2[g] = __floats2half2_rn(a.x + 0.5f * a.z, bx.x + 0.5f * bx.z);
            ty1_2[g] = __floats2half2_rn(a.y + 0.5f * a.w, bx.y + 0.5f * bx.w);
            ta_2[g]  = __floats2half2_rn(a.z * a.w,        bx.z * bx.w);
        }

        // one row: cls01/cls23 are half2 class costs for targets {0,1}/{2,3}
        auto eval_row = [&](int r, u32 cls01u, u32 cls23u) {
            const float4 f0 = s_pd[r][0];                 // 2x LDS.128 broadcast
            const float4 f1 = s_pd[r][1];
            const half2 pcx2  = h2_from_f(f0.x);
            const half2 pcy2  = h2_from_f(f0.y);
            const half2 pw2   = h2_from_f(f0.z);
            const half2 ph2   = h2_from_f(f0.w);
            const half2 px0_2 = h2_from_f(f1.x);
            const half2 py0_2 = h2_from_f(f1.y);
            const half2 px1_2 = h2_from_f(f1.z);
            const half2 py1_2 = h2_from_f(f1.w);
            const half2 pa_2  = __hmul2(pw2, ph2);
            const half2 cls[2] = { h2_from_u(cls01u), h2_from_u(cls23u) };

            half2 c2[2];
            #pragma unroll
            for (int g = 0; g < 2; g++) {
                half2 l15 = __hadd2(
                    __hadd2(__habs2(__hsub2(pcx2, tcx2[g])),
                            __habs2(__hsub2(pcy2, tcy2[g]))),
                    __hadd2(__habs2(__hsub2(pw2,  tw2[g])),
                            __habs2(__hsub2(ph2,  th2[g]))));
                half2 diw = __hsub2(__hmin2(px1_2, tx1_2[g]),
                                    __hmax2(px0_2, tx0_2[g]));
                half2 dih = __hsub2(__hmin2(py1_2, ty1_2[g]),
                                    __hmax2(py0_2, ty0_2[g]));
                half2 inter = __hmul2(__hmax2(diw, zero2), __hmax2(dih, zero2));
                half2 uni   = __hsub2(__hadd2(pa_2, ta_2[g]), inter);
                half2 ew  = __hsub2(__hadd2(pw2, tw2[g]), diw);
                half2 eh  = __hsub2(__hadd2(ph2, th2[g]), dih);
                half2 ea  = __hmul2(ew, eh);
                half2 tm  = __hfma2(uni, h2rcp(ea), __hmul2(inter, h2rcp(uni)));
                half2 h   = __hfma2(tm, m2, l15);         // 5*L1 - 2*(i/u+u/e)
                c2[g] = __hadd2(h, cls[g]);               // + (diff+2), fp16
            }
            reinterpret_cast<float4*>(out)[(n0 + r) * NQUAD + q] =
                make_float4(__low2float(c2[0]), __high2float(c2[0]),
                            __low2float(c2[1]), __high2float(c2[1]));
        };

        // ---- rows 0..7: 4 pairs, one LDS.U32 per id per pair ----
        #pragma unroll 1
        for (int p = 0; p < 4; p++) {
            const u32 A = pA[p], Bv = pB[p], C = pC[p], D = pD[p];
            eval_row(2 * p,     __byte_perm(A, Bv, 0x5410), __byte_perm(C, D, 0x5410));
            eval_row(2 * p + 1, __byte_perm(A, Bv, 0x7632), __byte_perm(C, D, 0x7632));
        }
        // ---- pair 4: row 8 always, row 9 only when R == 10 ----
        {
            const u32 A = pA[4], Bv = pB[4], C = pC[4], D = pD[4];
            eval_row(8, __byte_perm(A, Bv, 0x5410), __byte_perm(C, D, 0x5410));
            if (R == 10)
                eval_row(9, __byte_perm(A, Bv, 0x7632), __byte_perm(C, D, 0x7632));
        }
    }
}

// ---------------------------------------------------------------------------
extern "C" void kernel_launch(void* const* d_in, const int* in_sizes, int n_in,
                              void* d_out, int out_size)
{
    const float* pred_logits = (const float*)d_in[0];  // [16,1500,256]
    const float* pred_boxes  = (const float*)d_in[1];  // [16,1500,4]
    const float* tgt_bbox    = (const float*)d_in[2];  // [2400,4]
    const int*   tgt_ids     = (const int*)  d_in[3];  // [2400]
    float*       out         = (float*)d_out;          // [16,1500,2400]

    fused_kernel<<<NBLK, TPB>>>(pred_logits, pred_boxes, tgt_bbox,
                                tgt_ids, out);
}

// round 14
// speedup vs baseline: 1.0324x; 1.0214x over previous
#include <cuda_runtime.h>
#include <cuda_fp16.h>

// Problem constants
#define KCLS  256
#define NTOT  24000              // BS*Q rows
#define TTOT  2400               // targets
#define NPAIR (TTOT / 2)         // 1200 pairs of 2 targets
#define TPB   128
#define NBLK  2960               // 148 SMs x 10 blocks x 2 = EXACTLY two waves
#define RMAX  9                  // 320 blocks w/ 9 rows + 2640 w/ 8 = 24000

static __device__ __forceinline__ half2 h2_from_f(float f) {
    return *reinterpret_cast<half2*>(&f);
}
static __device__ __forceinline__ float f_from_h2(half2 h) {
    return *reinterpret_cast<float*>(&h);
}

// ---------------------------------------------------------------------------
// Fused kernel: one target-PAIR per thread (9 half2 splat regs, not 18) ->
// fits 10 blocks/SM for 62.5% occupancy ceiling. Block b owns rows
// [n0, n0+R), R in {8,9}. All geometry x5-scaled (L1 sum = 5*L1 directly;
// GIoU scale-invariant). fp32 class table + scalar LDS gathers (proven best).
// ---------------------------------------------------------------------------
__global__ __launch_bounds__(TPB, 10) void fused_kernel(
    const float* __restrict__ logits,       // [NTOT, 256]
    const float* __restrict__ pred_boxes,   // [NTOT, 4] cxcywh
    const float* __restrict__ tgt_bbox,     // [TTOT, 4] cxcywh
    const int*   __restrict__ tgt_ids,      // [TTOT]
    float*       __restrict__ out)          // [NTOT, TTOT]
{
    __shared__ float4 s_diff4[RMAX * KCLS / 4];    // 9216 B class-cost table
    __shared__ float4 s_pd[RMAX][2];               //  288 B pred splats

    const int tid = threadIdx.x;
    const int b   = blockIdx.x;
    const int n0  = b * 8 + min(b, 320);
    const int R   = (b < 320) ? 9 : 8;

    // ---- preamble A: class-cost table for R rows: focal(pos-neg)+2
    const float4* lg4 = reinterpret_cast<const float4*>(logits) + n0 * (KCLS / 4);
    for (int i = tid; i < R * (KCLS / 4); i += TPB) {
        float4 x4 = lg4[i];
        float4 o4;
        const float* xs = &x4.x;
        float*       os = &o4.x;
        #pragma unroll
        for (int j = 0; j < 4; j++) {
            float x   = xs[j];
            float ex  = __expf(-x);
            float L   = __logf(1.0f + ex);                // = -log(p)
            float p   = __frcp_rn(1.0f + ex);
            float omp = 1.0f - p;
            float pos = 0.25f * omp * omp * L;            // A(1-p)^2 * -log p
            float neg = 0.75f * p * p * (x + L);          // (1-A) p^2 * -log(1-p)
            os[j] = pos - neg + 2.0f;                     // +2 folds GIoU constant
        }
        s_diff4[i] = o4;
    }

    // ---- preamble B: pred boxes -> x5-scaled half2 splats
    if (tid < R) {
        float4 pb = reinterpret_cast<const float4*>(pred_boxes)[n0 + tid];
        pb.x *= 5.0f; pb.y *= 5.0f; pb.z *= 5.0f; pb.w *= 5.0f;
        s_pd[tid][0] = make_float4(f_from_h2(__float2half2_rn(pb.x)),
                                   f_from_h2(__float2half2_rn(pb.y)),
                                   f_from_h2(__float2half2_rn(pb.z)),
                                   f_from_h2(__float2half2_rn(pb.w)));
        s_pd[tid][1] = make_float4(f_from_h2(__float2half2_rn(pb.x - 0.5f * pb.z)),
                                   f_from_h2(__float2half2_rn(pb.y - 0.5f * pb.w)),
                                   f_from_h2(__float2half2_rn(pb.x + 0.5f * pb.z)),
                                   f_from_h2(__float2half2_rn(pb.y + 0.5f * pb.w)));
    }
    __syncthreads();

    const float* s_diff = reinterpret_cast<const float*>(s_diff4);
    const half2 zero2 = __float2half2_rn(0.0f);
    const half2 m2    = __float2half2_rn(-2.0f);

    for (int pp = tid; pp < NPAIR; pp += TPB) {
        // ---- one target pair: ids + x5-scaled half2 splats (9 regs) ----
        int2 id2 = reinterpret_cast<const int2*>(tgt_ids)[pp];
        float4 a  = reinterpret_cast<const float4*>(tgt_bbox)[2 * pp];
        float4 bx = reinterpret_cast<const float4*>(tgt_bbox)[2 * pp + 1];
        a.x *= 5.0f;  a.y *= 5.0f;  a.z *= 5.0f;  a.w *= 5.0f;
        bx.x *= 5.0f; bx.y *= 5.0f; bx.z *= 5.0f; bx.w *= 5.0f;
        const half2 tcx2 = __floats2half2_rn(a.x, bx.x);
        const half2 tcy2 = __floats2half2_rn(a.y, bx.y);
        const half2 tw2  = __floats2half2_rn(a.z, bx.z);
        const half2 th2  = __floats2half2_rn(a.w, bx.w);
        const half2 tx02 = __floats2half2_rn(a.x - 0.5f * a.z, bx.x - 0.5f * bx.z);
        const half2 ty02 = __floats2half2_rn(a.y - 0.5f * a.w, bx.y - 0.5f * bx.w);
        const half2 tx12 = __floats2half2_rn(a.x + 0.5f * a.z, bx.x + 0.5f * bx.z);
        const half2 ty12 = __floats2half2_rn(a.y + 0.5f * a.w, bx.y + 0.5f * bx.w);
        const half2 ta2  = __floats2half2_rn(a.z * a.w,        bx.z * bx.w);

        #pragma unroll 1
        for (int r = 0; r < R; r++) {
            const float4 f0 = s_pd[r][0];                 // 2x LDS.128 broadcast
            const float4 f1 = s_pd[r][1];
            const half2 pcx2  = h2_from_f(f0.x);
            const half2 pcy2  = h2_from_f(f0.y);
            const half2 pw2   = h2_from_f(f0.z);
            const half2 ph2   = h2_from_f(f0.w);
            const half2 px0_2 = h2_from_f(f1.x);
            const half2 py0_2 = h2_from_f(f1.y);
            const half2 px1_2 = h2_from_f(f1.z);
            const half2 py1_2 = h2_from_f(f1.w);
            const half2 pa_2  = __hmul2(pw2, ph2);
            const float* __restrict__ drow = s_diff + r * KCLS;

            // ---- 5*L1 (x5-scaled coords, half2, 2 targets) ----
            half2 l15 = __hadd2(
                __hadd2(__habs2(__hsub2(pcx2, tcx2)),
                        __habs2(__hsub2(pcy2, tcy2))),
                __hadd2(__habs2(__hsub2(pw2,  tw2)),
                        __habs2(__hsub2(ph2,  th2))));
            // ---- GIoU (scale-invariant) ----
            half2 diw = __hsub2(__hmin2(px1_2, tx12), __hmax2(px0_2, tx02));
            half2 dih = __hsub2(__hmin2(py1_2, ty12), __hmax2(py0_2, ty02));
            half2 inter = __hmul2(__hmax2(diw, zero2), __hmax2(dih, zero2));
            half2 uni   = __hsub2(__hadd2(pa_2, ta2), inter);
            half2 ew  = __hsub2(__hadd2(pw2, tw2), diw);
            half2 eh  = __hsub2(__hadd2(ph2, th2), dih);
            half2 ea  = __hmul2(ew, eh);
            half2 tm  = __hfma2(uni, h2rcp(ea), __hmul2(inter, h2rcp(uni)));
            // ---- fused: h = 5*L1 - 2*(i/u + u/e) ----
            half2 h = __hfma2(tm, m2, l15);

            float2 res;
            res.x = __low2float(h)  + drow[id2.x];        // + (diff+2) fp32
            res.y = __high2float(h) + drow[id2.y];
            reinterpret_cast<float2*>(out)[(n0 + r) * NPAIR + pp] = res;
        }
    }
}

// ---------------------------------------------------------------------------
extern "C" void kernel_launch(void* const* d_in, const int* in_sizes, int n_in,
                              void* d_out, int out_size)
{
    const float* pred_logits = (const float*)d_in[0];  // [16,1500,256]
    const float* pred_boxes  = (const float*)d_in[1];  // [16,1500,4]
    const float* tgt_bbox    = (const float*)d_in[2];  // [2400,4]
    const int*   tgt_ids     = (const int*)  d_in[3];  // [2400]
    float*       out         = (float*)d_out;          // [16,1500,2400]

    fused_kernel<<<NBLK, TPB>>>(pred_logits, pred_boxes, tgt_bbox,
                                tgt_ids, out);
}